// round 1
// baseline (speedup 1.0000x reference)
#include <cuda_runtime.h>
#include <cstdint>
#include <cstddef>

// Problem dims
#define BDIM 4096           // batch
#define KDIM 1024           // D_IN == H (contraction dim for both GEMMs)
#define HDIM 1024
#define NDIM (6*HDIM)       // 6 gates stacked -> 6144

// GEMM tiling
#define BM 128
#define BN 128
#define BK 32
#define ASTRIDE (BK+4)      // 36 floats -> 144B row stride: 16B aligned, conflict-free frags

// Scratch for the two [B, 6H] GEMM results (static device arrays: allowed)
__device__ float g_C1[(size_t)BDIM * NDIM];
__device__ float g_C2[(size_t)BDIM * NDIM];

__device__ __forceinline__ uint32_t f2tf32(float f) {
    uint32_t r;
    asm("cvt.rna.tf32.f32 %0, %1;" : "=r"(r) : "f"(f));
    return r;
}

__device__ __forceinline__ void cp_async16(void* smem_ptr, const void* gmem_ptr) {
    uint32_t s = (uint32_t)__cvta_generic_to_shared(smem_ptr);
    asm volatile("cp.async.cg.shared.global [%0], [%1], 16;\n" :: "r"(s), "l"(gmem_ptr));
}

// C[m][n] = sum_k A[m][k] * Bm[n][k]    (A: [4096,1024] row-major, Bm: [6144,1024] row-major)
__global__ __launch_bounds__(256, 2)
void gemm_tf32_kernel(const float* __restrict__ A, const float* __restrict__ Bm,
                      float* __restrict__ C) {
    extern __shared__ float smem[];
    float* As = smem;                         // [2][BM][ASTRIDE]
    float* Bs = smem + 2 * BM * ASTRIDE;      // [2][BN][ASTRIDE]

    const int tid  = threadIdx.x;
    const int warp = tid >> 5;
    const int lane = tid & 31;
    const int wm = warp & 1;       // 2 warps along M (64 rows each)
    const int wn = warp >> 1;      // 4 warps along N (32 cols each)
    const int g  = lane >> 2;      // 0..7
    const int tg = lane & 3;       // 0..3

    const int bm = blockIdx.y * BM;
    const int bn = blockIdx.x * BN;

    // cp.async load mapping: 256 threads, each 16B; 4 passes cover 128 rows x 32 cols
    const int lr = tid >> 3;           // 0..31
    const int lc = (tid & 7) * 4;      // 0,4,...,28

    float acc[4][4][4];
    #pragma unroll
    for (int mf = 0; mf < 4; mf++)
        #pragma unroll
        for (int nf = 0; nf < 4; nf++)
            #pragma unroll
            for (int r = 0; r < 4; r++) acc[mf][nf][r] = 0.0f;

    auto load_stage = [&](int s, int k0) {
        float* as = As + s * BM * ASTRIDE;
        float* bs = Bs + s * BM * ASTRIDE;
        #pragma unroll
        for (int p = 0; p < 4; p++) {
            int row = lr + p * 32;
            cp_async16(&as[row * ASTRIDE + lc], &A[(size_t)(bm + row) * KDIM + k0 + lc]);
            cp_async16(&bs[row * ASTRIDE + lc], &Bm[(size_t)(bn + row) * KDIM + k0 + lc]);
        }
        asm volatile("cp.async.commit_group;\n" ::: "memory");
    };

    load_stage(0, 0);
    const int nk = KDIM / BK;   // 32

    for (int kt = 0; kt < nk; kt++) {
        const int s = kt & 1;
        if (kt + 1 < nk) {
            load_stage(s ^ 1, (kt + 1) * BK);
            asm volatile("cp.async.wait_group 1;\n" ::: "memory");
        } else {
            asm volatile("cp.async.wait_group 0;\n" ::: "memory");
        }
        __syncthreads();

        const float* as = As + s * BM * ASTRIDE;
        const float* bs = Bs + s * BM * ASTRIDE;

        #pragma unroll
        for (int kk = 0; kk < BK; kk += 8) {
            uint32_t af[4][4];
            uint32_t bf[4][2];
            #pragma unroll
            for (int mf = 0; mf < 4; mf++) {
                int r0 = wm * 64 + mf * 16;
                af[mf][0] = f2tf32(as[(r0 + g)     * ASTRIDE + kk + tg]);
                af[mf][1] = f2tf32(as[(r0 + 8 + g) * ASTRIDE + kk + tg]);
                af[mf][2] = f2tf32(as[(r0 + g)     * ASTRIDE + kk + tg + 4]);
                af[mf][3] = f2tf32(as[(r0 + 8 + g) * ASTRIDE + kk + tg + 4]);
            }
            #pragma unroll
            for (int nf = 0; nf < 4; nf++) {
                int c0 = wn * 32 + nf * 8;
                bf[nf][0] = f2tf32(bs[(c0 + g) * ASTRIDE + kk + tg]);
                bf[nf][1] = f2tf32(bs[(c0 + g) * ASTRIDE + kk + tg + 4]);
            }
            #pragma unroll
            for (int mf = 0; mf < 4; mf++)
                #pragma unroll
                for (int nf = 0; nf < 4; nf++) {
                    asm volatile(
                        "mma.sync.aligned.m16n8k8.row.col.f32.tf32.tf32.f32 "
                        "{%0,%1,%2,%3}, {%4,%5,%6,%7}, {%8,%9}, {%0,%1,%2,%3};\n"
                        : "+f"(acc[mf][nf][0]), "+f"(acc[mf][nf][1]),
                          "+f"(acc[mf][nf][2]), "+f"(acc[mf][nf][3])
                        : "r"(af[mf][0]), "r"(af[mf][1]), "r"(af[mf][2]), "r"(af[mf][3]),
                          "r"(bf[nf][0]), "r"(bf[nf][1]));
                }
        }
        __syncthreads();
    }

    // Epilogue: write accumulators straight to global
    #pragma unroll
    for (int mf = 0; mf < 4; mf++) {
        #pragma unroll
        for (int nf = 0; nf < 4; nf++) {
            int row = bm + wm * 64 + mf * 16 + g;
            int col = bn + wn * 32 + nf * 8 + 2 * tg;
            C[(size_t)row * NDIM + col]           = acc[mf][nf][0];
            C[(size_t)row * NDIM + col + 1]       = acc[mf][nf][1];
            C[(size_t)(row + 8) * NDIM + col]     = acc[mf][nf][2];
            C[(size_t)(row + 8) * NDIM + col + 1] = acc[mf][nf][3];
        }
    }
}

__device__ __forceinline__ float sigmoidf_(float z) { return 1.0f / (1.0f + expf(-z)); }

__global__ __launch_bounds__(256)
void xlstm_epilogue_kernel(const float* __restrict__ c_prev,
                           const float* __restrict__ b_all,
                           float* __restrict__ out) {
    int idx = blockIdx.x * blockDim.x + threadIdx.x;
    if (idx >= BDIM * HDIM) return;
    int b = idx >> 10;        // / HDIM
    int h = idx & (HDIM - 1); // % HDIM
    size_t base = (size_t)b * NDIM + h;

    float wx[6], uh[6];
    #pragma unroll
    for (int k = 0; k < 6; k++) {
        wx[k] = g_C1[base + (size_t)k * HDIM] + b_all[k * HDIM + h];
        uh[k] = g_C2[base + (size_t)k * HDIM];
    }
    float i = sigmoidf_(wx[0] + uh[0]);
    float f = sigmoidf_(wx[1] + uh[1]);
    float o = sigmoidf_(wx[2] + uh[2]);
    float gg = tanhf(wx[3] + uh[3]);
    float m = wx[4] * uh[4];
    float a = sigmoidf_(wx[5] + uh[5]);

    float c_new = f * c_prev[idx] + i * gg + a * m;
    float h_new = o * tanhf(c_new);

    out[idx] = h_new;
    out[(size_t)BDIM * HDIM + idx] = c_new;
}

extern "C" void kernel_launch(void* const* d_in, const int* in_sizes, int n_in,
                              void* d_out, int out_size) {
    const float* x      = (const float*)d_in[0];
    const float* h_prev = (const float*)d_in[1];
    const float* c_prev = (const float*)d_in[2];
    const float* W_all  = (const float*)d_in[3];
    const float* b_all  = (const float*)d_in[4];
    const float* U_all  = (const float*)d_in[5];
    float* out = (float*)d_out;

    float *pC1 = nullptr, *pC2 = nullptr;
    cudaGetSymbolAddress((void**)&pC1, g_C1);
    cudaGetSymbolAddress((void**)&pC2, g_C2);

    const int smem_bytes = 4 * BM * ASTRIDE * sizeof(float);  // 2 stages x (A+B) = 73728 B
    cudaFuncSetAttribute(gemm_tf32_kernel,
                         cudaFuncAttributeMaxDynamicSharedMemorySize, smem_bytes);

    dim3 grid(NDIM / BN, BDIM / BM);   // 48 x 32
    gemm_tf32_kernel<<<grid, 256, smem_bytes>>>(x, W_all, pC1);
    gemm_tf32_kernel<<<grid, 256, smem_bytes>>>(h_prev, U_all, pC2);

    int n = BDIM * HDIM;
    xlstm_epilogue_kernel<<<(n + 255) / 256, 256>>>(c_prev, b_all, out);
}

// round 3
// speedup vs baseline: 1.3016x; 1.3016x over previous
#include <cuda_runtime.h>
#include <cstdint>
#include <cstddef>

// Problem dims
#define BDIM 4096
#define KDIM 1024
#define HDIM 1024
#define NDIM 6144           // 6 gates * H

// GEMM tiling
#define BM 128
#define BN 128
#define BK 32
#define SS 40               // smem row stride in floats (160B: 16B-aligned, LDS.64 conflict-free)
#define TILE_FLOATS (128 * SS)

// Scratch: Z[B,6H] (gate-4 slot holds wx4), U4[B,H] holds uh4
__device__ float g_Z[(size_t)BDIM * NDIM];
__device__ float g_U4[(size_t)BDIM * HDIM];

__device__ __forceinline__ void cp_async16(void* smem_ptr, const void* gmem_ptr) {
    uint32_t s = (uint32_t)__cvta_generic_to_shared(smem_ptr);
    asm volatile("cp.async.cg.shared.global [%0], [%1], 16;\n" :: "r"(s), "l"(gmem_ptr));
}

// One fused GEMM: Z = x*W^T + h*U^T (joint K=2048) for all gates; gate-4 tiles
// flush wx4 at the K midpoint and restart accumulation for uh4 -> U4.
__global__ __launch_bounds__(256, 2)
void xlstm_gemm_kernel(const float* __restrict__ xin, const float* __restrict__ hin,
                       const float* __restrict__ W,   const float* __restrict__ U,
                       float* __restrict__ Z, float* __restrict__ U4) {
    extern __shared__ float smem[];
    // layout: As[2][TILE_FLOATS], Bs[2][TILE_FLOATS]

    const int tid  = threadIdx.x;
    const int warp = tid >> 5;
    const int lane = tid & 31;
    const int wm = warp & 1;        // 2 warps along M (64 rows each)
    const int wn = warp >> 1;       // 4 warps along N (32 cols each)
    const int g  = lane >> 2;       // 0..7
    const int tg = lane & 3;        // 0..3

    const int bm = blockIdx.y * BM;
    const int bn = blockIdx.x * BN;
    const bool g4 = (blockIdx.x >= 32) && (blockIdx.x < 40);   // cols [4096,5120)

    // cp.async mapping: each thread owns one 16B chunk per row-group
    const int lr = tid >> 3;            // 0..31
    const int lc = (tid & 7) * 4;       // 0,4,...,28

    float acc[4][4][4];
    #pragma unroll
    for (int mf = 0; mf < 4; mf++)
        #pragma unroll
        for (int nf = 0; nf < 4; nf++)
            #pragma unroll
            for (int r = 0; r < 4; r++) acc[mf][nf][r] = 0.0f;

    auto load_stage = [&](int i, int s) {
        const float* Ag = (i < 32) ? xin : hin;
        const float* Bg = (i < 32) ? W : U;
        const int k0 = (i & 31) * BK + lc;
        float* as = smem + s * TILE_FLOATS;
        float* bs = smem + (2 + s) * TILE_FLOATS;
        #pragma unroll
        for (int p = 0; p < 4; p++) {
            int row = lr + p * 32;
            cp_async16(&as[row * SS + lc], &Ag[(size_t)(bm + row) * KDIM + k0]);
            cp_async16(&bs[row * SS + lc], &Bg[(size_t)(bn + row) * KDIM + k0]);
        }
        asm volatile("cp.async.commit_group;\n" ::: "memory");
    };

    auto flush = [&](float* dst, int ncols, int coloff) {
        #pragma unroll
        for (int mf = 0; mf < 4; mf++) {
            #pragma unroll
            for (int nf = 0; nf < 4; nf++) {
                int row = bm + wm * 64 + mf * 16 + g;
                int col = coloff + wn * 32 + nf * 8 + 2 * tg;
                *(float2*)&dst[(size_t)row * ncols + col] =
                    make_float2(acc[mf][nf][0], acc[mf][nf][1]);
                *(float2*)&dst[(size_t)(row + 8) * ncols + col] =
                    make_float2(acc[mf][nf][2], acc[mf][nf][3]);
            }
        }
    };

    load_stage(0, 0);
    const int nk = 64;   // 2 x (1024/32)

    for (int i = 0; i < nk; i++) {
        const int s = i & 1;
        if (i + 1 < nk) {
            load_stage(i + 1, s ^ 1);
            asm volatile("cp.async.wait_group 1;\n" ::: "memory");
        } else {
            asm volatile("cp.async.wait_group 0;\n" ::: "memory");
        }
        __syncthreads();

        // float2 views of the current stage
        const float2* as2 = (const float2*)(smem + s * TILE_FLOATS);
        const float2* bs2 = (const float2*)(smem + (2 + s) * TILE_FLOATS);
        const int SP = SS / 2;   // 20 float2 per row

        #pragma unroll
        for (int kk2 = 0; kk2 < BK / 2; kk2 += 4) {     // kk2 = kk/2 in {0,4,8,12}
            uint32_t af[4][4];
            uint32_t bf[4][2];
            // k-pair remap: slot pairs (a0,a2)/(b0,b1) read contiguous cols 2tg,2tg+1.
            // Same map for A and B => dot product unchanged (k-permutation invariant).
            #pragma unroll
            for (int mf = 0; mf < 4; mf++) {
                int r0 = wm * 64 + mf * 16 + g;
                float2 lo = as2[r0 * SP + kk2 + tg];
                float2 hi = as2[(r0 + 8) * SP + kk2 + tg];
                af[mf][0] = __float_as_uint(lo.x);
                af[mf][2] = __float_as_uint(lo.y);
                af[mf][1] = __float_as_uint(hi.x);
                af[mf][3] = __float_as_uint(hi.y);
            }
            #pragma unroll
            for (int nf = 0; nf < 4; nf++) {
                int c0 = wn * 32 + nf * 8 + g;
                float2 b = bs2[c0 * SP + kk2 + tg];
                bf[nf][0] = __float_as_uint(b.x);
                bf[nf][1] = __float_as_uint(b.y);
            }
            #pragma unroll
            for (int mf = 0; mf < 4; mf++)
                #pragma unroll
                for (int nf = 0; nf < 4; nf++) {
                    asm volatile(
                        "mma.sync.aligned.m16n8k8.row.col.f32.tf32.tf32.f32 "
                        "{%0,%1,%2,%3}, {%4,%5,%6,%7}, {%8,%9}, {%0,%1,%2,%3};\n"
                        : "+f"(acc[mf][nf][0]), "+f"(acc[mf][nf][1]),
                          "+f"(acc[mf][nf][2]), "+f"(acc[mf][nf][3])
                        : "r"(af[mf][0]), "r"(af[mf][1]), "r"(af[mf][2]), "r"(af[mf][3]),
                          "r"(bf[nf][0]), "r"(bf[nf][1]));
                }
        }
        __syncthreads();

        // Gate-4 midpoint flush: wx4 complete after first 32 k-tiles
        if (g4 && i == 31) {
            flush(Z, NDIM, bn);
            #pragma unroll
            for (int mf = 0; mf < 4; mf++)
                #pragma unroll
                for (int nf = 0; nf < 4; nf++)
                    #pragma unroll
                    for (int r = 0; r < 4; r++) acc[mf][nf][r] = 0.0f;
        }
    }

    if (g4) flush(U4, HDIM, bn - 4096);   // uh4
    else    flush(Z, NDIM, bn);           // wx + uh
}

__device__ __forceinline__ float sigmoidf_(float z) { return 1.0f / (1.0f + expf(-z)); }

__global__ __launch_bounds__(256)
void xlstm_epilogue_kernel(const float* __restrict__ c_prev,
                           const float* __restrict__ b_all,
                           float* __restrict__ out) {
    int idx = blockIdx.x * blockDim.x + threadIdx.x;
    if (idx >= BDIM * HDIM) return;
    int b = idx >> 10;
    int h = idx & (HDIM - 1);
    size_t base = (size_t)b * NDIM + h;

    float z0 = g_Z[base]        + b_all[h];
    float z1 = g_Z[base + 1024] + b_all[1024 + h];
    float z2 = g_Z[base + 2048] + b_all[2048 + h];
    float z3 = g_Z[base + 3072] + b_all[3072 + h];
    float z4 = g_Z[base + 4096] + b_all[4096 + h];   // wx4 (+bias)
    float z5 = g_Z[base + 5120] + b_all[5120 + h];
    float u4 = g_U4[idx];                            // uh4

    float i = sigmoidf_(z0);
    float f = sigmoidf_(z1);
    float o = sigmoidf_(z2);
    float gg = tanhf(z3);
    float m = z4 * u4;
    float a = sigmoidf_(z5);

    float c_new = f * c_prev[idx] + i * gg + a * m;
    float h_new = o * tanhf(c_new);

    out[idx] = h_new;
    out[(size_t)BDIM * HDIM + idx] = c_new;
}

extern "C" void kernel_launch(void* const* d_in, const int* in_sizes, int n_in,
                              void* d_out, int out_size) {
    const float* x      = (const float*)d_in[0];
    const float* h_prev = (const float*)d_in[1];
    const float* c_prev = (const float*)d_in[2];
    const float* W_all  = (const float*)d_in[3];
    const float* b_all  = (const float*)d_in[4];
    const float* U_all  = (const float*)d_in[5];
    float* out = (float*)d_out;

    float *pZ = nullptr, *pU4 = nullptr;
    cudaGetSymbolAddress((void**)&pZ, g_Z);
    cudaGetSymbolAddress((void**)&pU4, g_U4);

    const int smem_bytes = 4 * TILE_FLOATS * sizeof(float);   // 81920 B
    cudaFuncSetAttribute(xlstm_gemm_kernel,
                         cudaFuncAttributeMaxDynamicSharedMemorySize, smem_bytes);

    dim3 grid(NDIM / BN, BDIM / BM);   // 48 x 32
    xlstm_gemm_kernel<<<grid, 256, smem_bytes>>>(x, h_prev, W_all, U_all, pZ, pU4);

    int n = BDIM * HDIM;
    xlstm_epilogue_kernel<<<(n + 255) / 256, 256>>>(c_prev, b_all, out);
}